// round 1
// baseline (speedup 1.0000x reference)
#include <cuda_runtime.h>
#include <cstdint>

// Problem constants
#define B   32
#define C   256
#define H   56
#define W   56
#define OH  28
#define OW  28
#define CO  256           // outputs per half
#define NW  8             // 256 bits -> 8 uint32 words
#define NPIX (B*OH*OW)    // 25088 positions per half
#define NELEM_PER_C (B*H*W)  // 100352

// -------- device scratch (no allocations allowed) --------
__device__ float    g_partial[C][8][2];          // per (channel, chunk): sum, sumsq
__device__ float    g_thr[C];
__device__ int      g_mode[C];                   // 0: x>=thr, 1: x<=thr, 2: always +1, 3: always -1
__device__ unsigned g_wpack[2*CO][NW];           // rows 0..255 = w1, 256..511 = w2
__device__ unsigned g_apack[2][NPIX * NW];       // [half][pos*8 + word]

// ============================================================
// Kernel 1: per-(channel, batch-chunk) partial sums (deterministic)
// grid (256, 8), block 256
// ============================================================
__global__ __launch_bounds__(256) void stats_kernel(const float* __restrict__ x) {
    int c = blockIdx.x;
    int chunk = blockIdx.y;            // 4 batches per chunk
    float s = 0.f, sq = 0.f;
    for (int b = chunk * 4; b < chunk * 4 + 4; b++) {
        const float4* p = reinterpret_cast<const float4*>(x + ((size_t)b * C + c) * (H * W));
        for (int i = threadIdx.x; i < (H * W) / 4; i += 256) {
            float4 v = p[i];
            s  += v.x + v.y + v.z + v.w;
            sq += v.x * v.x + v.y * v.y + v.z * v.z + v.w * v.w;
        }
    }
    __shared__ float ss[256], sb[256];
    ss[threadIdx.x] = s; sb[threadIdx.x] = sq;
    __syncthreads();
    for (int o = 128; o > 0; o >>= 1) {
        if (threadIdx.x < o) {
            ss[threadIdx.x] += ss[threadIdx.x + o];
            sb[threadIdx.x] += sb[threadIdx.x + o];
        }
        __syncthreads();
    }
    if (threadIdx.x == 0) {
        g_partial[c][chunk][0] = ss[0];
        g_partial[c][chunk][1] = sb[0];
    }
}

// ============================================================
// Kernel 2: bit-pack weights. bit=1 <=> w >= 0 (binarize -> +1)
// grid 64, block 256 (8 warps/block, 1 row per warp, 512 rows)
// ============================================================
__global__ __launch_bounds__(256) void wpack_kernel(const float* __restrict__ w1,
                                                    const float* __restrict__ w2) {
    int warp = (blockIdx.x * blockDim.x + threadIdx.x) >> 5;   // 0..511
    int lane = threadIdx.x & 31;
    const float* w = (warp < CO) ? (w1 + (size_t)warp * C)
                                 : (w2 + (size_t)(warp - CO) * C);
    #pragma unroll
    for (int j = 0; j < NW; j++) {
        float v = w[j * 32 + lane];
        unsigned m = __ballot_sync(0xffffffffu, v >= 0.f);
        if (lane == 0) g_wpack[warp][j] = m;
    }
}

// ============================================================
// Kernel 3: finalize stats -> per-channel threshold + compare mode
// 1 block, 256 threads
// ============================================================
__global__ __launch_bounds__(256) void thr_kernel(const float* __restrict__ gamma,
                                                  const float* __restrict__ beta) {
    int c = threadIdx.x;
    float s = 0.f, sq = 0.f;
    #pragma unroll
    for (int k = 0; k < 8; k++) { s += g_partial[c][k][0]; sq += g_partial[c][k][1]; }
    const float N = (float)NELEM_PER_C;
    float mean = s / N;
    float var  = sq / N - mean * mean;
    if (var < 0.f) var = 0.f;
    float inv = rsqrtf(var + 1e-5f);
    float g = gamma[c], bt = beta[c];
    int mode; float thr = 0.f;
    if (g > 0.f)      { mode = 0; thr = mean - bt / (inv * g); }   // xn>=0 <=> x>=thr
    else if (g < 0.f) { mode = 1; thr = mean - bt / (inv * g); }   // xn>=0 <=> x<=thr
    else              { mode = (bt >= 0.f) ? 2 : 3; }              // constant sign
    g_thr[c]  = thr;
    g_mode[c] = mode;
}

// ============================================================
// Kernel 4: binarize + bit-pack activations (channel transpose via ballot)
// grid (B, OH, 2 halves), block 256 = 8 warps; warp j owns channels 32j..32j+31
// half 0: rows ::2 cols ::2 ; half 1: rows 1::2 cols 1::2
// ============================================================
__global__ __launch_bounds__(256) void apack_kernel(const float* __restrict__ x) {
    int b = blockIdx.x, oh = blockIdx.y, half = blockIdx.z;
    int wj   = threadIdx.x >> 5;
    int lane = threadIdx.x & 31;
    int c = wj * 32 + lane;
    int h = 2 * oh + half;
    const float* p = x + (((size_t)b * C + c) * H + h) * W + half;
    float thr = g_thr[c];
    int   mode = g_mode[c];
    unsigned* outp = &g_apack[half][(((size_t)b * OH + oh) * OW) * NW + wj];
    #pragma unroll 4
    for (int ow = 0; ow < OW; ow++) {
        float v = p[2 * ow];
        bool pred = (mode == 0) ? (v >= thr)
                  : (mode == 1) ? (v <= thr)
                  : (mode == 2);
        unsigned m = __ballot_sync(0xffffffffu, pred);
        if (lane == 0) outp[(size_t)ow * NW] = m;
    }
}

// ============================================================
// Kernel 5: XNOR-popcount GEMM.  out[b, half*256+o, oh, ow]
// grid (B, OH, 2), block 256 as (32 lanes = ow, 8 = o-phase)
// dot = 256 - 2*popc(a ^ w)
// ============================================================
__global__ __launch_bounds__(256) void gemm_kernel(float* __restrict__ out) {
    int b = blockIdx.x, oh = blockIdx.y, half = blockIdx.z;
    __shared__ unsigned sw[CO * NW];   // 8 KB: this half's packed weights
    __shared__ unsigned sa[OW * NW];   // 896 B: this (b, oh) act row

    const unsigned* wsrc = &g_wpack[half * CO][0];
    for (int i = threadIdx.x; i < CO * NW; i += 256) sw[i] = wsrc[i];
    const unsigned* asrc = &g_apack[half][(((size_t)b * OH + oh) * OW) * NW];
    for (int i = threadIdx.x; i < OW * NW; i += 256) sa[i] = asrc[i];
    __syncthreads();

    int tx = threadIdx.x & 31;   // ow lane
    int ty = threadIdx.x >> 5;   // o phase 0..7
    if (tx >= OW) return;

    unsigned a0 = sa[tx * NW + 0], a1 = sa[tx * NW + 1],
             a2 = sa[tx * NW + 2], a3 = sa[tx * NW + 3],
             a4 = sa[tx * NW + 4], a5 = sa[tx * NW + 5],
             a6 = sa[tx * NW + 6], a7 = sa[tx * NW + 7];

    float* op = out + ((((size_t)b * 2 * CO + half * CO) * OH + oh) * OW) + tx;
    #pragma unroll 8
    for (int oo = 0; oo < CO / 8; oo++) {
        int o = oo * 8 + ty;
        const unsigned* w = &sw[o * NW];
        int s = __popc(a0 ^ w[0]) + __popc(a1 ^ w[1])
              + __popc(a2 ^ w[2]) + __popc(a3 ^ w[3])
              + __popc(a4 ^ w[4]) + __popc(a5 ^ w[5])
              + __popc(a6 ^ w[6]) + __popc(a7 ^ w[7]);
        op[(size_t)o * (OH * OW)] = (float)(C - 2 * s);
    }
}

// ============================================================
extern "C" void kernel_launch(void* const* d_in, const int* in_sizes, int n_in,
                              void* d_out, int out_size) {
    const float* x     = (const float*)d_in[0];
    const float* gamma = (const float*)d_in[1];
    const float* beta  = (const float*)d_in[2];
    const float* w1    = (const float*)d_in[3];
    const float* w2    = (const float*)d_in[4];
    float* out = (float*)d_out;

    stats_kernel<<<dim3(C, 8), 256>>>(x);
    wpack_kernel<<<64, 256>>>(w1, w2);          // independent of stats
    thr_kernel<<<1, 256>>>(gamma, beta);        // after stats (stream-ordered)
    apack_kernel<<<dim3(B, OH, 2), 256>>>(x);   // after thr
    gemm_kernel<<<dim3(B, OH, 2), 256>>>(out);  // after apack + wpack
}

// round 2
// speedup vs baseline: 1.3765x; 1.3765x over previous
#include <cuda_runtime.h>
#include <cstdint>

// Problem constants
#define B   32
#define C   256
#define H   56
#define W   56
#define OH  28
#define OW  28
#define CO  256           // outputs per half
#define NW  8             // 256 bits -> 8 uint32 words
#define NPIX (B*OH*OW)    // 25088 positions per half
#define NELEM_PER_C (B*H*W)  // 100352

// -------- device scratch (no allocations allowed) --------
__device__ float    g_partial[C][8][2];          // per (channel, chunk): sum, sumsq
__device__ float    g_lo[C];                     // binarize window: +1 iff lo <= v <= hi
__device__ float    g_hi[C];
__device__ unsigned g_wpack[2*CO][NW];           // rows 0..255 = w1, 256..511 = w2
__device__ unsigned g_apack[2][NPIX * NW];       // [half][pos*8 + word]

// ============================================================
// Kernel 1: per-(channel, batch-chunk) partial sums (deterministic)
// grid (256, 8), block 256
// ============================================================
__global__ __launch_bounds__(256) void stats_kernel(const float* __restrict__ x) {
    int c = blockIdx.x;
    int chunk = blockIdx.y;            // 4 batches per chunk
    float s = 0.f, sq = 0.f;
    for (int b = chunk * 4; b < chunk * 4 + 4; b++) {
        const float4* p = reinterpret_cast<const float4*>(x + ((size_t)b * C + c) * (H * W));
        for (int i = threadIdx.x; i < (H * W) / 4; i += 256) {
            float4 v = p[i];
            s  += v.x + v.y + v.z + v.w;
            sq += v.x * v.x + v.y * v.y + v.z * v.z + v.w * v.w;
        }
    }
    __shared__ float ss[256], sb[256];
    ss[threadIdx.x] = s; sb[threadIdx.x] = sq;
    __syncthreads();
    for (int o = 128; o > 0; o >>= 1) {
        if (threadIdx.x < o) {
            ss[threadIdx.x] += ss[threadIdx.x + o];
            sb[threadIdx.x] += sb[threadIdx.x + o];
        }
        __syncthreads();
    }
    if (threadIdx.x == 0) {
        g_partial[c][chunk][0] = ss[0];
        g_partial[c][chunk][1] = sb[0];
    }
}

// ============================================================
// Kernel 2: bit-pack weights. bit=1 <=> w >= 0 (binarize -> +1)
// grid 64, block 256 (8 warps/block, 1 row per warp, 512 rows)
// ============================================================
__global__ __launch_bounds__(256) void wpack_kernel(const float* __restrict__ w1,
                                                    const float* __restrict__ w2) {
    int warp = (blockIdx.x * blockDim.x + threadIdx.x) >> 5;   // 0..511
    int lane = threadIdx.x & 31;
    const float* w = (warp < CO) ? (w1 + (size_t)warp * C)
                                 : (w2 + (size_t)(warp - CO) * C);
    #pragma unroll
    for (int j = 0; j < NW; j++) {
        float v = w[j * 32 + lane];
        unsigned m = __ballot_sync(0xffffffffu, v >= 0.f);
        if (lane == 0) g_wpack[warp][j] = m;
    }
}

// ============================================================
// Kernel 3: finalize stats -> per-channel [lo, hi] binarize window
// +1 iff lo <= x <= hi  (branchless in the hot kernel)
//   gamma>0: x >= thr  -> [thr, +inf]
//   gamma<0: x <= thr  -> [-inf, thr]
//   gamma=0: sign(beta) -> [-inf,+inf] or [+inf,-inf] (never true)
// 1 block, 256 threads
// ============================================================
__global__ __launch_bounds__(256) void thr_kernel(const float* __restrict__ gamma,
                                                  const float* __restrict__ beta) {
    int c = threadIdx.x;
    float s = 0.f, sq = 0.f;
    #pragma unroll
    for (int k = 0; k < 8; k++) { s += g_partial[c][k][0]; sq += g_partial[c][k][1]; }
    const float N = (float)NELEM_PER_C;
    float mean = s / N;
    float var  = sq / N - mean * mean;
    if (var < 0.f) var = 0.f;
    float inv = rsqrtf(var + 1e-5f);
    float g = gamma[c], bt = beta[c];
    const float INF = __int_as_float(0x7f800000);
    float lo, hi;
    if (g > 0.f)      { lo = mean - bt / (inv * g); hi =  INF; }
    else if (g < 0.f) { hi = mean - bt / (inv * g); lo = -INF; }
    else if (bt >= 0.f) { lo = -INF; hi =  INF; }
    else                { lo =  INF; hi = -INF; }
    g_lo[c] = lo;
    g_hi[c] = hi;
}

// ============================================================
// Kernel 4: binarize + bit-pack activations — COALESCED version.
// grid (B, OH, 2 halves), block 256 = 8 warps.
// Phase 1: warp j walks channels j*32..j*32+31; lane k<28 loads float2 #k of
//          the W-row (fully coalesced 224B burst); picks .x/.y by half parity;
//          stores predicate byte to s[c][k].
// Phase 2: warp j = packed word j; 28 ballots over s[j*32+lane][k]; masks
//          staged in smem; one coalesced 896B store.
// ============================================================
__global__ __launch_bounds__(256) void apack_kernel(const float* __restrict__ x) {
    int b = blockIdx.x, oh = blockIdx.y, half = blockIdx.z;
    int j    = threadIdx.x >> 5;
    int lane = threadIdx.x & 31;
    int h = 2 * oh + half;

    __shared__ unsigned char s[C][OW];   // 7 KB predicate matrix (conflict-free)
    __shared__ float  slo[C], shi[C];
    __shared__ unsigned m[OW * NW];      // 896 B staged masks

    slo[threadIdx.x] = g_lo[threadIdx.x];
    shi[threadIdx.x] = g_hi[threadIdx.x];
    __syncthreads();

    // ---- Phase 1: coalesced reads + predicate bytes ----
    if (lane < OW) {
        const size_t rowstep = (size_t)H * W;      // channel stride in floats
        const float* base = x + (((size_t)b * C + j * 32) * H + h) * W;
        #pragma unroll 4
        for (int r = 0; r < 32; r++) {
            int c = j * 32 + r;
            float2 v = reinterpret_cast<const float2*>(base + r * rowstep)[lane];
            float val = half ? v.y : v.x;
            s[c][lane] = (val >= slo[c]) && (val <= shi[c]);
        }
    }
    __syncthreads();

    // ---- Phase 2: channel-transpose via ballot ----
    #pragma unroll 4
    for (int k = 0; k < OW; k++) {
        unsigned mask = __ballot_sync(0xffffffffu, s[j * 32 + lane][k] != 0);
        if (lane == 0) m[k * NW + j] = mask;
    }
    __syncthreads();

    // ---- coalesced 896B store ----
    unsigned* dst = &g_apack[half][(((size_t)b * OH + oh) * OW) * NW];
    if (threadIdx.x < OW * NW) dst[threadIdx.x] = m[threadIdx.x];
}

// ============================================================
// Kernel 5: XNOR-popcount GEMM.  out[b, half*256+o, oh, ow]
// grid (B, OH, 2), block 256 as (32 lanes = ow, 8 = o-phase)
// dot = 256 - 2*popc(a ^ w)
// ============================================================
__global__ __launch_bounds__(256) void gemm_kernel(float* __restrict__ out) {
    int b = blockIdx.x, oh = blockIdx.y, half = blockIdx.z;
    __shared__ unsigned sw[CO * NW];   // 8 KB: this half's packed weights
    __shared__ unsigned sa[OW * NW];   // 896 B: this (b, oh) act row

    const unsigned* wsrc = &g_wpack[half * CO][0];
    for (int i = threadIdx.x; i < CO * NW; i += 256) sw[i] = wsrc[i];
    const unsigned* asrc = &g_apack[half][(((size_t)b * OH + oh) * OW) * NW];
    for (int i = threadIdx.x; i < OW * NW; i += 256) sa[i] = asrc[i];
    __syncthreads();

    int tx = threadIdx.x & 31;   // ow lane
    int ty = threadIdx.x >> 5;   // o phase 0..7
    if (tx >= OW) return;

    unsigned a0 = sa[tx * NW + 0], a1 = sa[tx * NW + 1],
             a2 = sa[tx * NW + 2], a3 = sa[tx * NW + 3],
             a4 = sa[tx * NW + 4], a5 = sa[tx * NW + 5],
             a6 = sa[tx * NW + 6], a7 = sa[tx * NW + 7];

    float* op = out + ((((size_t)b * 2 * CO + half * CO) * OH + oh) * OW) + tx;
    #pragma unroll 8
    for (int oo = 0; oo < CO / 8; oo++) {
        int o = oo * 8 + ty;
        const unsigned* w = &sw[o * NW];
        int s = __popc(a0 ^ w[0]) + __popc(a1 ^ w[1])
              + __popc(a2 ^ w[2]) + __popc(a3 ^ w[3])
              + __popc(a4 ^ w[4]) + __popc(a5 ^ w[5])
              + __popc(a6 ^ w[6]) + __popc(a7 ^ w[7]);
        op[(size_t)o * (OH * OW)] = (float)(C - 2 * s);
    }
}

// ============================================================
extern "C" void kernel_launch(void* const* d_in, const int* in_sizes, int n_in,
                              void* d_out, int out_size) {
    const float* x     = (const float*)d_in[0];
    const float* gamma = (const float*)d_in[1];
    const float* beta  = (const float*)d_in[2];
    const float* w1    = (const float*)d_in[3];
    const float* w2    = (const float*)d_in[4];
    float* out = (float*)d_out;

    stats_kernel<<<dim3(C, 8), 256>>>(x);
    wpack_kernel<<<64, 256>>>(w1, w2);          // independent of stats
    thr_kernel<<<1, 256>>>(gamma, beta);        // after stats (stream-ordered)
    apack_kernel<<<dim3(B, OH, 2), 256>>>(x);   // after thr
    gemm_kernel<<<dim3(B, OH, 2), 256>>>(out);  // after apack + wpack
}

// round 3
// speedup vs baseline: 1.3795x; 1.0022x over previous
#include <cuda_runtime.h>
#include <cstdint>

// Problem constants
#define B   32
#define C   256
#define H   56
#define W   56
#define OH  28
#define OW  28
#define CO  256           // outputs per half
#define NW  8             // 256 bits -> 8 uint32 words
#define NPIX (B*OH*OW)    // 25088 positions per half
#define NELEM_PER_C (B*H*W)  // 100352

// -------- device scratch (no allocations allowed) --------
__device__ float    g_partial[C][B][2];          // per (channel, batch): sum, sumsq
__device__ float    g_lo[C];                     // binarize window: +1 iff lo <= v <= hi
__device__ float    g_hi[C];
__device__ unsigned g_wpack[2*CO][NW];           // rows 0..255 = w1, 256..511 = w2
__device__ unsigned g_apack[2][NPIX * NW];       // [half][pos*8 + word]

// ============================================================
// Kernel 1: per-(b,c)-plane partial sums. One warp per plane.
// grid 1024, block 256 (8 warps). 8192 planes total.
// Plane = 3136 floats = 784 float4; lane strides by 32.
// ============================================================
__global__ __launch_bounds__(256) void stats_kernel(const float* __restrict__ x) {
    int wid  = (blockIdx.x * blockDim.x + threadIdx.x) >> 5;  // plane id 0..8191
    int lane = threadIdx.x & 31;
    int b = wid >> 8;          // 0..31
    int c = wid & 255;         // 0..255
    const float4* p = reinterpret_cast<const float4*>(x + ((size_t)b * C + c) * (H * W));

    float s0 = 0.f, s1 = 0.f, q0 = 0.f, q1 = 0.f;
    #pragma unroll 4
    for (int i = lane; i < (H * W) / 4; i += 32) {
        float4 v = p[i];
        s0 += v.x + v.y;
        s1 += v.z + v.w;
        q0 += v.x * v.x + v.y * v.y;
        q1 += v.z * v.z + v.w * v.w;
    }
    float s = s0 + s1, q = q0 + q1;
    #pragma unroll
    for (int o = 16; o > 0; o >>= 1) {
        s += __shfl_down_sync(0xffffffffu, s, o);
        q += __shfl_down_sync(0xffffffffu, q, o);
    }
    if (lane == 0) {
        g_partial[c][b][0] = s;
        g_partial[c][b][1] = q;
    }
}

// ============================================================
// Kernel 2: bit-pack weights. bit=1 <=> w >= 0 (binarize -> +1)
// grid 64, block 256 (8 warps/block, 1 row per warp, 512 rows)
// ============================================================
__global__ __launch_bounds__(256) void wpack_kernel(const float* __restrict__ w1,
                                                    const float* __restrict__ w2) {
    int warp = (blockIdx.x * blockDim.x + threadIdx.x) >> 5;   // 0..511
    int lane = threadIdx.x & 31;
    const float* w = (warp < CO) ? (w1 + (size_t)warp * C)
                                 : (w2 + (size_t)(warp - CO) * C);
    #pragma unroll
    for (int j = 0; j < NW; j++) {
        float v = w[j * 32 + lane];
        unsigned m = __ballot_sync(0xffffffffu, v >= 0.f);
        if (lane == 0) g_wpack[warp][j] = m;
    }
}

// ============================================================
// Kernel 3: finalize stats -> per-channel [lo, hi] binarize window
// +1 iff lo <= x <= hi  (branchless in the hot kernel)
// 1 block, 256 threads; sequential (deterministic) reduce over 32 batches
// ============================================================
__global__ __launch_bounds__(256) void thr_kernel(const float* __restrict__ gamma,
                                                  const float* __restrict__ beta) {
    int c = threadIdx.x;
    float s = 0.f, sq = 0.f;
    #pragma unroll
    for (int k = 0; k < B; k++) { s += g_partial[c][k][0]; sq += g_partial[c][k][1]; }
    const float N = (float)NELEM_PER_C;
    float mean = s / N;
    float var  = sq / N - mean * mean;
    if (var < 0.f) var = 0.f;
    float inv = rsqrtf(var + 1e-5f);
    float g = gamma[c], bt = beta[c];
    const float INF = __int_as_float(0x7f800000);
    float lo, hi;
    if (g > 0.f)      { lo = mean - bt / (inv * g); hi =  INF; }
    else if (g < 0.f) { hi = mean - bt / (inv * g); lo = -INF; }
    else if (bt >= 0.f) { lo = -INF; hi =  INF; }
    else                { lo =  INF; hi = -INF; }
    g_lo[c] = lo;
    g_hi[c] = hi;
}

// ============================================================
// Kernel 4: binarize + bit-pack activations — register transpose.
// grid (B, OH, 2 halves), block 256 = 8 warps.
// Warp j owns packed word j (channels 32j..32j+31). Lane k<28 owns output
// position k: it accumulates its own 32-bit word across the channel loop
// (bit r = channel 32j+r). Loads are coalesced 224B bursts per row; no smem,
// no ballots, no __syncthreads.
// ============================================================
__global__ __launch_bounds__(256) void apack_kernel(const float* __restrict__ x) {
    int b = blockIdx.x, oh = blockIdx.y, half = blockIdx.z;
    int j    = threadIdx.x >> 5;
    int lane = threadIdx.x & 31;
    int h = 2 * oh + half;

    if (lane >= OW) return;

    const size_t rowstep = (size_t)H * W;      // channel stride in floats
    const float* base = x + (((size_t)b * C + j * 32) * H + h) * W;

    unsigned bits = 0;
    #pragma unroll 8
    for (int r = 0; r < 32; r++) {
        int c = j * 32 + r;
        float2 v = reinterpret_cast<const float2*>(base + r * rowstep)[lane];
        float val = half ? v.y : v.x;
        bool pred = (val >= g_lo[c]) && (val <= g_hi[c]);
        bits |= (pred ? 1u : 0u) << r;
    }

    unsigned* dst = &g_apack[half][(((size_t)b * OH + oh) * OW) * NW];
    dst[(size_t)lane * NW + j] = bits;
}

// ============================================================
// Kernel 5: XNOR-popcount GEMM.  out[b, half*256+o, oh, ow]
// grid (B, OH, 2), block 256 as (32 lanes = ow, 8 = o-phase)
// dot = 256 - 2*popc(a ^ w)
// ============================================================
__global__ __launch_bounds__(256) void gemm_kernel(float* __restrict__ out) {
    int b = blockIdx.x, oh = blockIdx.y, half = blockIdx.z;
    __shared__ unsigned sw[CO * NW];   // 8 KB: this half's packed weights
    __shared__ unsigned sa[OW * NW];   // 896 B: this (b, oh) act row

    const unsigned* wsrc = &g_wpack[half * CO][0];
    for (int i = threadIdx.x; i < CO * NW; i += 256) sw[i] = wsrc[i];
    const unsigned* asrc = &g_apack[half][(((size_t)b * OH + oh) * OW) * NW];
    for (int i = threadIdx.x; i < OW * NW; i += 256) sa[i] = asrc[i];
    __syncthreads();

    int tx = threadIdx.x & 31;   // ow lane
    int ty = threadIdx.x >> 5;   // o phase 0..7
    if (tx >= OW) return;

    unsigned a0 = sa[tx * NW + 0], a1 = sa[tx * NW + 1],
             a2 = sa[tx * NW + 2], a3 = sa[tx * NW + 3],
             a4 = sa[tx * NW + 4], a5 = sa[tx * NW + 5],
             a6 = sa[tx * NW + 6], a7 = sa[tx * NW + 7];

    float* op = out + ((((size_t)b * 2 * CO + half * CO) * OH + oh) * OW) + tx;
    #pragma unroll 8
    for (int oo = 0; oo < CO / 8; oo++) {
        int o = oo * 8 + ty;
        const unsigned* w = &sw[o * NW];
        int s = __popc(a0 ^ w[0]) + __popc(a1 ^ w[1])
              + __popc(a2 ^ w[2]) + __popc(a3 ^ w[3])
              + __popc(a4 ^ w[4]) + __popc(a5 ^ w[5])
              + __popc(a6 ^ w[6]) + __popc(a7 ^ w[7]);
        op[(size_t)o * (OH * OW)] = (float)(C - 2 * s);
    }
}

// ============================================================
extern "C" void kernel_launch(void* const* d_in, const int* in_sizes, int n_in,
                              void* d_out, int out_size) {
    const float* x     = (const float*)d_in[0];
    const float* gamma = (const float*)d_in[1];
    const float* beta  = (const float*)d_in[2];
    const float* w1    = (const float*)d_in[3];
    const float* w2    = (const float*)d_in[4];
    float* out = (float*)d_out;

    stats_kernel<<<1024, 256>>>(x);
    wpack_kernel<<<64, 256>>>(w1, w2);          // independent of stats
    thr_kernel<<<1, 256>>>(gamma, beta);        // after stats (stream-ordered)
    apack_kernel<<<dim3(B, OH, 2), 256>>>(x);   // after thr
    gemm_kernel<<<dim3(B, OH, 2), 256>>>(out);  // after apack + wpack
}

// round 4
// speedup vs baseline: 1.8493x; 1.3405x over previous
#include <cuda_runtime.h>
#include <cstdint>

// Problem constants
#define B   32
#define C   256
#define H   56
#define W   56
#define OH  28
#define OW  28
#define CO  256           // outputs per half
#define NW  8             // 256 bits -> 8 uint32 words
#define NELEM_PER_C (B*H*W)  // 100352

// -------- device scratch (no allocations allowed) --------
__device__ float    g_partial[C][B][2];          // per (channel, batch): sum, sumsq
__device__ float    g_lo[C];                     // binarize window: +1 iff lo <= v <= hi
__device__ float    g_hi[C];
__device__ int      g_fast;                      // 1 if all gamma > 0 (lo-only compare)
__device__ unsigned g_wpack[2*CO][NW];           // rows 0..255 = w1, 256..511 = w2

// ============================================================
// Kernel 1: stats partials (one warp per (b,c) plane) + weight pack.
// grid 1088: blocks 0..1023 stats, 1024..1087 wpack.
// ============================================================
__global__ __launch_bounds__(256) void stats_wpack_kernel(const float* __restrict__ x,
                                                          const float* __restrict__ w1,
                                                          const float* __restrict__ w2) {
    int lane = threadIdx.x & 31;
    if (blockIdx.x >= 1024) {
        // ---- weight pack: 8 warps/block, one 256-wide row per warp ----
        int warp = ((blockIdx.x - 1024) * 256 + threadIdx.x) >> 5;   // 0..511
        const float* w = (warp < CO) ? (w1 + (size_t)warp * C)
                                     : (w2 + (size_t)(warp - CO) * C);
        #pragma unroll
        for (int j = 0; j < NW; j++) {
            float v = w[j * 32 + lane];
            unsigned m = __ballot_sync(0xffffffffu, v >= 0.f);
            if (lane == 0) g_wpack[warp][j] = m;
        }
        return;
    }
    // ---- stats: plane id = warp id ----
    int wid = (blockIdx.x * 256 + threadIdx.x) >> 5;  // 0..8191
    int b = wid >> 8, c = wid & 255;
    const float4* p = reinterpret_cast<const float4*>(x + ((size_t)b * C + c) * (H * W));
    float s0 = 0.f, s1 = 0.f, q0 = 0.f, q1 = 0.f;
    #pragma unroll 4
    for (int i = lane; i < (H * W) / 4; i += 32) {
        float4 v = p[i];
        s0 += v.x + v.y;
        s1 += v.z + v.w;
        q0 += v.x * v.x + v.y * v.y;
        q1 += v.z * v.z + v.w * v.w;
    }
    float s = s0 + s1, q = q0 + q1;
    #pragma unroll
    for (int o = 16; o > 0; o >>= 1) {
        s += __shfl_down_sync(0xffffffffu, s, o);
        q += __shfl_down_sync(0xffffffffu, q, o);
    }
    if (lane == 0) {
        g_partial[c][b][0] = s;
        g_partial[c][b][1] = q;
    }
}

// ============================================================
// Kernel 2: finalize stats -> per-channel [lo, hi] window + fast flag
// 1 block, 256 threads; deterministic sequential reduce over batches
// ============================================================
__global__ __launch_bounds__(256) void thr_kernel(const float* __restrict__ gamma,
                                                  const float* __restrict__ beta) {
    int c = threadIdx.x;
    float s = 0.f, sq = 0.f;
    #pragma unroll
    for (int k = 0; k < B; k++) { s += g_partial[c][k][0]; sq += g_partial[c][k][1]; }
    const float N = (float)NELEM_PER_C;
    float mean = s / N;
    float var  = sq / N - mean * mean;
    if (var < 0.f) var = 0.f;
    float inv = rsqrtf(var + 1e-5f);
    float g = gamma[c], bt = beta[c];
    const float INF = __int_as_float(0x7f800000);
    float lo, hi;
    if (g > 0.f)      { lo = mean - bt / (inv * g); hi =  INF; }
    else if (g < 0.f) { hi = mean - bt / (inv * g); lo = -INF; }
    else if (bt >= 0.f) { lo = -INF; hi =  INF; }
    else                { lo =  INF; hi = -INF; }
    g_lo[c] = lo;
    g_hi[c] = hi;

    // all-gamma-positive? (lo-only compare fast path)
    __shared__ int sflag;
    if (threadIdx.x == 0) sflag = 1;
    __syncthreads();
    unsigned warp_ok = __ballot_sync(0xffffffffu, g > 0.f);
    if ((threadIdx.x & 31) == 0 && warp_ok != 0xffffffffu) atomicAnd(&sflag, 0);
    __syncthreads();
    if (threadIdx.x == 0) g_fast = sflag;
}

// ============================================================
// Kernel 3 (FUSED): binarize+pack into smem, then XNOR-popcount GEMM.
// grid (B, OH, 2 halves), block 256 = 8 warps.
// Phase A: warp j packs word j (channels 32j..32j+31); lane k = output
//          position k accumulates its own 32-bit word (bit r = channel 32j+r).
//          Coalesced float2 row reads. Masks -> smem sa[pix*8+j].
// Phase B: 8 KB weight stage -> popc GEMM, lanes = ow (coalesced stores).
// ============================================================
__global__ __launch_bounds__(256) void fused_kernel(const float* __restrict__ x,
                                                    float* __restrict__ out) {
    int b = blockIdx.x, oh = blockIdx.y, half = blockIdx.z;
    int j    = threadIdx.x >> 5;
    int lane = threadIdx.x & 31;
    int h = 2 * oh + half;

    __shared__ unsigned sa[OW * NW];   // 896 B packed activations for this (b,oh,half)
    __shared__ unsigned sw[CO * NW];   // 8 KB packed weights for this half

    // ---- stage weights (independent of phase A) ----
    const unsigned* wsrc = &g_wpack[half * CO][0];
    #pragma unroll
    for (int i = 0; i < (CO * NW) / 256; i++)
        sw[i * 256 + threadIdx.x] = wsrc[i * 256 + threadIdx.x];

    // ---- Phase A: binarize + register-pack ----
    {
        const size_t rowstep = (size_t)H * W;
        int k = lane < OW ? lane : OW - 1;            // clamp so all lanes can shfl
        const float* base = x + (((size_t)b * C + j * 32) * H + h) * W;
        unsigned bits = 0;
        if (g_fast) {
            float lo_mine = g_lo[j * 32 + lane];      // one value per lane
            #pragma unroll 8
            for (int r = 0; r < 32; r++) {
                float2 v = reinterpret_cast<const float2*>(base + r * rowstep)[k];
                float val = half ? v.y : v.x;
                float lo_r = __shfl_sync(0xffffffffu, lo_mine, r);
                bits |= (val >= lo_r ? 1u : 0u) << r;
            }
        } else {
            #pragma unroll 8
            for (int r = 0; r < 32; r++) {
                int c = j * 32 + r;
                float2 v = reinterpret_cast<const float2*>(base + r * rowstep)[k];
                float val = half ? v.y : v.x;
                bool pred = (val >= g_lo[c]) && (val <= g_hi[c]);
                bits |= (pred ? 1u : 0u) << r;
            }
        }
        if (lane < OW) sa[lane * NW + j] = bits;
    }
    __syncthreads();

    // ---- Phase B: popcount GEMM ----
    int tx = lane;            // ow
    int ty = j;               // o-phase 0..7
    if (tx >= OW) return;

    unsigned a0 = sa[tx * NW + 0], a1 = sa[tx * NW + 1],
             a2 = sa[tx * NW + 2], a3 = sa[tx * NW + 3],
             a4 = sa[tx * NW + 4], a5 = sa[tx * NW + 5],
             a6 = sa[tx * NW + 6], a7 = sa[tx * NW + 7];

    float* op = out + ((((size_t)b * 2 * CO + half * CO) * OH + oh) * OW) + tx;
    #pragma unroll 8
    for (int oo = 0; oo < CO / 8; oo++) {
        int o = oo * 8 + ty;
        const unsigned* w = &sw[o * NW];
        int s = __popc(a0 ^ w[0]) + __popc(a1 ^ w[1])
              + __popc(a2 ^ w[2]) + __popc(a3 ^ w[3])
              + __popc(a4 ^ w[4]) + __popc(a5 ^ w[5])
              + __popc(a6 ^ w[6]) + __popc(a7 ^ w[7]);
        op[(size_t)o * (OH * OW)] = (float)(C - 2 * s);
    }
}

// ============================================================
extern "C" void kernel_launch(void* const* d_in, const int* in_sizes, int n_in,
                              void* d_out, int out_size) {
    const float* x     = (const float*)d_in[0];
    const float* gamma = (const float*)d_in[1];
    const float* beta  = (const float*)d_in[2];
    const float* w1    = (const float*)d_in[3];
    const float* w2    = (const float*)d_in[4];
    float* out = (float*)d_out;

    stats_wpack_kernel<<<1088, 256>>>(x, w1, w2);
    thr_kernel<<<1, 256>>>(gamma, beta);
    fused_kernel<<<dim3(B, OH, 2), 256>>>(x, out);
}